// round 16
// baseline (speedup 1.0000x reference)
#include <cuda_runtime.h>
#include <cuda_fp16.h>
#include <cstdint>
#include <cstddef>

// ---------------------------------------------------------------------------
// VQ quantizer via mma.sync (HMMA) fp16 double-split GEMM (fp32-accurate dot).
// 16 warps, M32xN32 warp tiles; A split-0 fragments hoisted into registers,
// A split-1 reloaded per chunk; B via ldmatrix + TMA bulk double buffer with
// full/empty mbarrier pipeline.
//   z (NT x 64) vs codebook (1024 x 64)
//   outputs (concat f32): e[NT], z_q[NT*64], sim[NT*K], loss[NT]
//   warp = (mgrp 0..3) x (ncol 0..3)
// ---------------------------------------------------------------------------

#define D        64
#define BM       128                 // tokens per CTA
#define BN       128                 // codes per chunk
#define KTOT     1024
#define NCHUNK   (KTOT / BN)         // 8
#define THREADS  512

#define ROWB     144u                // padded row: 64 fp16 (128B) + 16B pad
#define SPLIT_B  (128u * ROWB)       // 18432 B per split tile
#define CHUNK_B  (2u * SPLIT_B)      // 36864 B per chunk (2 splits)

#define OFF_A    0u                  // A splits: 2 x 18432 = 36864
#define OFF_B0   36864u
#define OFF_B1   73728u
#define OFF_PAIR 110592u             // 8192 B: (en2, einv) float2 per code
#define OFF_ZN   118784u             // 512 B
#define OFF_ZI   119296u             // 512 B
#define OFF_MD   119808u             // 4 x 128 f32 = 2048
#define OFF_MI   121856u             // 4 x 128 int = 2048
#define OFF_MBAR 123904u             // full0, full1, empty0, empty1
#define SMEM_REQ 123968u

__device__ __forceinline__ void ldsm_x4(uint32_t* r, unsigned addr) {
    asm volatile("ldmatrix.sync.aligned.m8n8.x4.shared.b16 {%0,%1,%2,%3}, [%4];"
                 : "=r"(r[0]), "=r"(r[1]), "=r"(r[2]), "=r"(r[3]) : "r"(addr));
}

__device__ __forceinline__ void mma16816(float* d, const uint32_t* a, const uint32_t* b) {
    asm volatile(
        "mma.sync.aligned.m16n8k16.row.col.f32.f16.f16.f32 "
        "{%0,%1,%2,%3}, {%4,%5,%6,%7}, {%8,%9}, {%0,%1,%2,%3};"
        : "+f"(d[0]), "+f"(d[1]), "+f"(d[2]), "+f"(d[3])
        : "r"(a[0]), "r"(a[1]), "r"(a[2]), "r"(a[3]), "r"(b[0]), "r"(b[1]));
}

#define MBAR_INIT(addr, cnt) \
    asm volatile("mbarrier.init.shared.b64 [%0], %1;" :: "r"(addr), "r"(cnt) : "memory")
#define MBAR_EXPECT_TX(addr, bytes) \
    asm volatile("mbarrier.arrive.expect_tx.shared.b64 _, [%0], %1;" \
                 :: "r"(addr), "r"(bytes) : "memory")
#define MBAR_ARRIVE(addr) \
    asm volatile("mbarrier.arrive.shared.b64 _, [%0];" :: "r"(addr) : "memory")
#define MBAR_WAIT(addr, ph) \
    asm volatile("{\n\t.reg .pred P;\n\tWL%=:\n\t" \
                 "mbarrier.try_wait.parity.shared.b64 P, [%0], %1;\n\t" \
                 "@!P bra WL%=;\n\t}" :: "r"(addr), "r"(ph) : "memory")
#define BULK_G2S(dst, src, bytes, mbar) \
    asm volatile("cp.async.bulk.shared::cluster.global.mbarrier::complete_tx::bytes " \
                 "[%0], [%1], %2, [%3];" \
                 :: "r"(dst), "l"(src), "r"(bytes), "r"(mbar) : "memory")

// ---------------- prep: norms + padded fp16 split images --------------------
__device__ __align__(16) unsigned short g_bsplit[NCHUNK * 2 * 128 * 72];
__device__ __align__(16) float2 g_pairs[KTOT];    // (en2, einv)

__global__ void vq_prep(const float* __restrict__ cbk) {
    int idx = blockIdx.x * blockDim.x + threadIdx.x;   // 0 .. KTOT*D-1
    if (idx >= KTOT * D) return;
    int code = idx >> 6, d = idx & 63;
    int c = code >> 7, r = code & 127;
    float x = cbk[idx];
    __half h0 = __float2half_rn(x);
    float r1 = x - __half2float(h0);
    __half h1 = __float2half_rn(r1);
    unsigned basei = (unsigned)(c * 2) * 9216u + (unsigned)r * 72u + (unsigned)d;
    g_bsplit[basei]         = __half_as_ushort(h0);
    g_bsplit[basei + 9216u] = __half_as_ushort(h1);

    if (idx < KTOT) {
        const float4* row = reinterpret_cast<const float4*>(cbk + (size_t)idx * D);
        float s = 0.f;
#pragma unroll
        for (int i = 0; i < D / 4; ++i) {
            float4 v = row[i];
            s += v.x * v.x + v.y * v.y + v.z * v.z + v.w * v.w;
        }
        g_pairs[idx] = make_float2(s, rsqrtf(s));
    }
}

// ---------------- main kernel ------------------------------------------------
__global__ void __launch_bounds__(THREADS, 1)
vq_mma_kernel(const float* __restrict__ z,
              const float* __restrict__ cbk,
              float* __restrict__ e_out,
              float* __restrict__ zq_out,
              float* __restrict__ sim_out,
              float* __restrict__ loss_out) {
    extern __shared__ unsigned char smp[];
    unsigned base;
    asm("{ .reg .u64 t; cvta.to.shared.u64 t, %1; cvt.u32.u64 %0, t; }"
        : "=r"(base) : "l"((void*)smp));

    const int tid   = threadIdx.x;
    const int lane  = tid & 31;
    const int warp  = tid >> 5;
    const int quad  = lane >> 2;     // 0..7
    const int qlane = lane & 3;      // 0..3
    const int mgrp  = warp & 3;      // token row group (32 rows)
    const int ncol  = warp >> 2;     // 32-code column group

    float2* pairs  = (float2*)(smp + OFF_PAIR);
    float*  znorms = (float*)(smp + OFF_ZN);
    float*  zinvs  = (float*)(smp + OFF_ZI);
    float*  mindS  = (float*)(smp + OFF_MD);   // [4][128]
    int*    miniS  = (int*)(smp + OFF_MI);     // [4][128]
    const unsigned full0  = base + OFF_MBAR;
    const unsigned full1  = full0 + 8;
    const unsigned empty0 = full0 + 16;
    const unsigned empty1 = full0 + 24;

    if (tid == 0) {
        MBAR_INIT(full0, 1);  MBAR_INIT(full1, 1);
        MBAR_INIT(empty0, THREADS); MBAR_INIT(empty1, THREADS);
    }
    __syncthreads();

    // ---- single-thread bulk loads of B chunks 0 and 1 -------------------
    if (tid == 0) {
        const char* gb = (const char*)g_bsplit;
        MBAR_EXPECT_TX(full0, CHUNK_B);
        BULK_G2S(base + OFF_B0, gb, CHUNK_B, full0);
        MBAR_EXPECT_TX(full1, CHUNK_B);
        BULK_G2S(base + OFF_B1, gb + CHUNK_B, CHUNK_B, full1);
    }

    // ---- (en2, einv) pair table into smem --------------------------------
    for (int k = tid; k < KTOT; k += THREADS) pairs[k] = g_pairs[k];

    // ---- build A split tiles (thread t<128 owns token-row t) ------------
    if (tid < BM) {
        const size_t tok = (size_t)blockIdx.x * BM + tid;
        const float4* zr = reinterpret_cast<const float4*>(z + tok * D);
        float zn = 0.f;
#pragma unroll
        for (int q = 0; q < 16; ++q) {
            float4 v = zr[q];
            zn += v.x * v.x + v.y * v.y + v.z * v.z + v.w * v.w;
            float xs[4] = {v.x, v.y, v.z, v.w};
            unsigned long long p0 = 0, p1 = 0;
#pragma unroll
            for (int j = 0; j < 4; ++j) {
                float x = xs[j];
                __half h0 = __float2half_rn(x);
                float rr1 = x - __half2float(h0);
                __half h1 = __float2half_rn(rr1);
                p0 |= (unsigned long long)__half_as_ushort(h0) << (16 * j);
                p1 |= (unsigned long long)__half_as_ushort(h1) << (16 * j);
            }
            unsigned off = (unsigned)tid * ROWB + (unsigned)q * 8u;
            *(unsigned long long*)(smp + OFF_A + 0 * SPLIT_B + off) = p0;
            *(unsigned long long*)(smp + OFF_A + 1 * SPLIT_B + off) = p1;
        }
        znorms[tid] = zn;
        zinvs[tid]  = rsqrtf(zn);
    }
    __syncthreads();     // A tiles + norms visible to all warps

    // ---- HOIST: load A split-0 fragments ONCE into registers ------------
    const unsigned aoff = (unsigned)(lane & 15) * ROWB + (unsigned)((lane >> 4) & 1) * 16u;
    const unsigned aBase0 = base + OFF_A + (unsigned)(mgrp * 32) * ROWB + aoff;
    uint32_t A0[2][4][4];          // [mi][kk][frag]  (split 0 only)
#pragma unroll
    for (int mi = 0; mi < 2; ++mi)
#pragma unroll
        for (int kk = 0; kk < 4; ++kk)
            ldsm_x4(A0[mi][kk], aBase0 + (unsigned)(mi * 16) * ROWB + (unsigned)kk * 32u);

    // this thread's 4 token rows: mi in {0,1}, rowpair in {0,1}
    int rows[2][2];
    float znr[2][2], zir[2][2];
    float* simP[2][2];
#pragma unroll
    for (int mi = 0; mi < 2; ++mi)
#pragma unroll
        for (int rp = 0; rp < 2; ++rp) {
            int r = mgrp * 32 + mi * 16 + rp * 8 + quad;
            rows[mi][rp] = r;
            znr[mi][rp] = znorms[r];
            zir[mi][rp] = zinvs[r];
            simP[mi][rp] = sim_out + ((size_t)blockIdx.x * BM + r) * (size_t)KTOT;
        }

    float mind[2][2] = {{3.4e38f, 3.4e38f}, {3.4e38f, 3.4e38f}};
    int   mini[2][2] = {{0, 0}, {0, 0}};

    const unsigned boff = ((unsigned)(lane & 7) + (unsigned)((lane >> 4) & 1) * 8u) * ROWB
                        + (unsigned)((lane >> 3) & 1) * 16u;
    const unsigned bColOff = (unsigned)(ncol * 32) * ROWB + boff;

#pragma unroll 1
    for (int c = 0; c < NCHUNK; ++c) {
        const int b = c & 1;
        const unsigned ph = (unsigned)((c >> 1) & 1);
        MBAR_WAIT(b ? full1 : full0, ph);

        const unsigned Bb = base + (b ? OFF_B1 : OFF_B0) + bColOff;

        float acc[2][4][4];      // [mi][nj][quad-frag]
#pragma unroll
        for (int mi = 0; mi < 2; ++mi)
#pragma unroll
            for (int nj = 0; nj < 4; ++nj)
#pragma unroll
                for (int j = 0; j < 4; ++j) acc[mi][nj][j] = 0.f;

#pragma unroll
        for (int kk = 0; kk < 4; ++kk) {
            // A split-1 fragments for this kk (reloaded each chunk)
            uint32_t A1[2][4];
#pragma unroll
            for (int mi = 0; mi < 2; ++mi)
                ldsm_x4(A1[mi], aBase0 + (unsigned)(mi * 16) * ROWB
                                + SPLIT_B + (unsigned)kk * 32u);

#pragma unroll
            for (int sb = 0; sb < 2; ++sb) {
                uint32_t Bf[2][4];   // [n16-group][frag]
#pragma unroll
                for (int g = 0; g < 2; ++g)
                    ldsm_x4(Bf[g], Bb + (unsigned)sb * SPLIT_B
                                   + (unsigned)(g * 16) * ROWB + (unsigned)kk * 32u);

                // products: (a0,b0), (a1,b0), (a0,b1)   (drop a1b1 ~ 2^-22)
#pragma unroll
                for (int mi = 0; mi < 2; ++mi)
#pragma unroll
                    for (int g = 0; g < 2; ++g) {
                        mma16816(acc[mi][2 * g],     A0[mi][kk], &Bf[g][0]);
                        mma16816(acc[mi][2 * g + 1], A0[mi][kk], &Bf[g][2]);
                        if (sb == 0) {
                            mma16816(acc[mi][2 * g],     A1[mi], &Bf[g][0]);
                            mma16816(acc[mi][2 * g + 1], A1[mi], &Bf[g][2]);
                        }
                    }
            }
        }

        // done reading buffer b -> signal empty (no block barrier)
        MBAR_ARRIVE(b ? empty1 : empty0);

        // producer: refill buffer b with chunk c+2 once all warps released it
        if (c + 2 < NCHUNK && tid == 0) {
            MBAR_WAIT(b ? empty1 : empty0, ph);
            const char* gb = (const char*)g_bsplit + (size_t)(c + 2) * CHUNK_B;
            MBAR_EXPECT_TX(b ? full1 : full0, CHUNK_B);
            BULK_G2S(base + (b ? OFF_B1 : OFF_B0), gb, CHUNK_B, b ? full1 : full0);
        }

        // ---- epilogue from registers (overlaps other warps' MMAs) -------
        const int cbase = c * BN + ncol * 32;
#pragma unroll
        for (int nj = 0; nj < 4; ++nj) {
            const int gci = cbase + nj * 8 + qlane * 2;
            float4 pv = *reinterpret_cast<const float4*>(pairs + gci);
#pragma unroll
            for (int mi = 0; mi < 2; ++mi) {
                const float d00 = acc[mi][nj][0], d01 = acc[mi][nj][1];
                const float d10 = acc[mi][nj][2], d11 = acc[mi][nj][3];
                float t;
                t = fmaf(-2.f, d00, znr[mi][0]) + pv.x;
                if (t < mind[mi][0]) { mind[mi][0] = t; mini[mi][0] = gci; }
                t = fmaf(-2.f, d01, znr[mi][0]) + pv.z;
                if (t < mind[mi][0]) { mind[mi][0] = t; mini[mi][0] = gci + 1; }
                t = fmaf(-2.f, d10, znr[mi][1]) + pv.x;
                if (t < mind[mi][1]) { mind[mi][1] = t; mini[mi][1] = gci; }
                t = fmaf(-2.f, d11, znr[mi][1]) + pv.z;
                if (t < mind[mi][1]) { mind[mi][1] = t; mini[mi][1] = gci + 1; }
                __stcs(reinterpret_cast<float2*>(simP[mi][0] + gci),
                       make_float2(d00 * zir[mi][0] * pv.y, d01 * zir[mi][0] * pv.w));
                __stcs(reinterpret_cast<float2*>(simP[mi][1] + gci),
                       make_float2(d10 * zir[mi][1] * pv.y, d11 * zir[mi][1] * pv.w));
            }
        }
    }

    // ---- argmin reduce across qlane (lanes differ in bits 0..1) ---------
#pragma unroll
    for (int mi = 0; mi < 2; ++mi)
#pragma unroll
        for (int rp = 0; rp < 2; ++rp) {
            float d = mind[mi][rp];
            int   i = mini[mi][rp];
#pragma unroll
            for (int off = 1; off <= 2; off <<= 1) {
                float od = __shfl_xor_sync(0xffffffffu, d, off);
                int   oi = __shfl_xor_sync(0xffffffffu, i, off);
                if (od < d || (od == d && oi < i)) { d = od; i = oi; }
            }
            if (qlane == 0) {
                mindS[ncol * 128 + rows[mi][rp]] = d;
                miniS[ncol * 128 + rows[mi][rp]] = i;
            }
        }
    __syncthreads();

    // ---- final per-token outputs: e, z_q, loss (fp32 from global) ------
    if (tid < BM) {
        float bd = mindS[tid];
        int   bi = miniS[tid];
#pragma unroll
        for (int s = 1; s < 4; ++s) {
            float d = mindS[s * 128 + tid];
            int   i = miniS[s * 128 + tid];
            if (d < bd || (d == bd && i < bi)) { bd = d; bi = i; }
        }
        const size_t tok = (size_t)blockIdx.x * BM + tid;
        const float4* er = reinterpret_cast<const float4*>(cbk + (size_t)bi * D);
        const float4* zr = reinterpret_cast<const float4*>(z + tok * D);
        float4* zq = reinterpret_cast<float4*>(zq_out + tok * D);
        float s = 0.f;
#pragma unroll
        for (int q = 0; q < 16; ++q) {
            float4 ev = er[q];
            float4 zv = zr[q];
            float dx = zv.x - ev.x, dy = zv.y - ev.y, dz = zv.z - ev.z, dw = zv.w - ev.w;
            s += dx * dx + dy * dy + dz * dz + dw * dw;
            zq[q] = ev;
        }
        loss_out[tok] = 1.25f * sqrtf(s);
        e_out[tok]    = (float)bi;
    }
}

extern "C" void kernel_launch(void* const* d_in, const int* in_sizes, int n_in,
                              void* d_out, int out_size) {
    const float* z   = (const float*)d_in[0];
    const float* cbk = (const float*)d_in[1];
    const int NT = in_sizes[0] / D;    // 131072

    float* out      = (float*)d_out;
    float* e_out    = out;
    float* zq_out   = e_out + NT;
    float* sim_out  = zq_out + (size_t)NT * D;
    float* loss_out = sim_out + (size_t)NT * KTOT;

    vq_prep<<<(KTOT * D + 255) / 256, 256>>>(cbk);

    cudaFuncSetAttribute(vq_mma_kernel, cudaFuncAttributeMaxDynamicSharedMemorySize, SMEM_REQ);
    vq_mma_kernel<<<NT / BM, THREADS, SMEM_REQ>>>(z, cbk, e_out, zq_out, sim_out, loss_out);
}

// round 17
// speedup vs baseline: 1.0211x; 1.0211x over previous
#include <cuda_runtime.h>
#include <cuda_fp16.h>
#include <cstdint>
#include <cstddef>

// ---------------------------------------------------------------------------
// VQ quantizer via mma.sync (HMMA) fp16 double-split GEMM (fp32-accurate dot).
// 8 warps, M32xN64 warp tiles, A fragments hoisted into registers (loaded
// once); B via ldmatrix + TMA bulk with THREE buffers (full/empty mbarrier
// pipeline, warps free-run up to 2 chunks of skew).
//   z (NT x 64) vs codebook (1024 x 64)
//   outputs (concat f32): e[NT], z_q[NT*64], sim[NT*K], loss[NT]
// ---------------------------------------------------------------------------

#define D        64
#define BM       128                 // tokens per CTA
#define BN       128                 // codes per chunk
#define KTOT     1024
#define NCHUNK   (KTOT / BN)         // 8
#define NBUF     3
#define THREADS  256

#define ROWB     144u                // padded row: 64 fp16 (128B) + 16B pad
#define SPLIT_B  (128u * ROWB)       // 18432 B per split tile
#define CHUNK_B  (2u * SPLIT_B)      // 36864 B per chunk (2 splits)

#define OFF_A    0u                  // A splits: 2 x 18432 = 36864
#define OFF_B    36864u              // 3 buffers x 36864 = 110592
#define OFF_PAIR 147456u             // 8192 B: (en2, einv) float2 per code
#define OFF_ZN   155648u             // 512 B
#define OFF_ZI   156160u             // 512 B
#define OFF_MD   156672u             // 2 x 128 f32 = 1024
#define OFF_MI   157696u             // 2 x 128 int = 1024
#define OFF_MBAR 158720u             // full0..2, empty0..2 (6 x 8 B)
#define SMEM_REQ 158784u

__device__ __forceinline__ void ldsm_x4(uint32_t* r, unsigned addr) {
    asm volatile("ldmatrix.sync.aligned.m8n8.x4.shared.b16 {%0,%1,%2,%3}, [%4];"
                 : "=r"(r[0]), "=r"(r[1]), "=r"(r[2]), "=r"(r[3]) : "r"(addr));
}

__device__ __forceinline__ void mma16816(float* d, const uint32_t* a, const uint32_t* b) {
    asm volatile(
        "mma.sync.aligned.m16n8k16.row.col.f32.f16.f16.f32 "
        "{%0,%1,%2,%3}, {%4,%5,%6,%7}, {%8,%9}, {%0,%1,%2,%3};"
        : "+f"(d[0]), "+f"(d[1]), "+f"(d[2]), "+f"(d[3])
        : "r"(a[0]), "r"(a[1]), "r"(a[2]), "r"(a[3]), "r"(b[0]), "r"(b[1]));
}

#define MBAR_INIT(addr, cnt) \
    asm volatile("mbarrier.init.shared.b64 [%0], %1;" :: "r"(addr), "r"(cnt) : "memory")
#define MBAR_EXPECT_TX(addr, bytes) \
    asm volatile("mbarrier.arrive.expect_tx.shared.b64 _, [%0], %1;" \
                 :: "r"(addr), "r"(bytes) : "memory")
#define MBAR_ARRIVE(addr) \
    asm volatile("mbarrier.arrive.shared.b64 _, [%0];" :: "r"(addr) : "memory")
#define MBAR_WAIT(addr, ph) \
    asm volatile("{\n\t.reg .pred P;\n\tWL%=:\n\t" \
                 "mbarrier.try_wait.parity.shared.b64 P, [%0], %1;\n\t" \
                 "@!P bra WL%=;\n\t}" :: "r"(addr), "r"(ph) : "memory")
#define BULK_G2S(dst, src, bytes, mbar) \
    asm volatile("cp.async.bulk.shared::cluster.global.mbarrier::complete_tx::bytes " \
                 "[%0], [%1], %2, [%3];" \
                 :: "r"(dst), "l"(src), "r"(bytes), "r"(mbar) : "memory")

// ---------------- prep: norms + padded fp16 split images --------------------
__device__ __align__(16) unsigned short g_bsplit[NCHUNK * 2 * 128 * 72];
__device__ __align__(16) float2 g_pairs[KTOT];    // (en2, einv)

__global__ void vq_prep(const float* __restrict__ cbk) {
    int idx = blockIdx.x * blockDim.x + threadIdx.x;   // 0 .. KTOT*D-1
    if (idx >= KTOT * D) return;
    int code = idx >> 6, d = idx & 63;
    int c = code >> 7, r = code & 127;
    float x = cbk[idx];
    __half h0 = __float2half_rn(x);
    float r1 = x - __half2float(h0);
    __half h1 = __float2half_rn(r1);
    unsigned basei = (unsigned)(c * 2) * 9216u + (unsigned)r * 72u + (unsigned)d;
    g_bsplit[basei]         = __half_as_ushort(h0);
    g_bsplit[basei + 9216u] = __half_as_ushort(h1);

    if (idx < KTOT) {
        const float4* row = reinterpret_cast<const float4*>(cbk + (size_t)idx * D);
        float s = 0.f;
#pragma unroll
        for (int i = 0; i < D / 4; ++i) {
            float4 v = row[i];
            s += v.x * v.x + v.y * v.y + v.z * v.z + v.w * v.w;
        }
        g_pairs[idx] = make_float2(s, rsqrtf(s));
    }
}

// ---------------- main kernel ------------------------------------------------
__global__ void __launch_bounds__(THREADS, 1)
vq_mma_kernel(const float* __restrict__ z,
              const float* __restrict__ cbk,
              float* __restrict__ e_out,
              float* __restrict__ zq_out,
              float* __restrict__ sim_out,
              float* __restrict__ loss_out) {
    extern __shared__ unsigned char smp[];
    unsigned base;
    asm("{ .reg .u64 t; cvta.to.shared.u64 t, %1; cvt.u32.u64 %0, t; }"
        : "=r"(base) : "l"((void*)smp));

    const int tid   = threadIdx.x;
    const int lane  = tid & 31;
    const int warp  = tid >> 5;
    const int quad  = lane >> 2;     // 0..7
    const int qlane = lane & 3;      // 0..3
    const int mgrp  = warp & 3;      // token row group (32 rows)
    const int ncol  = warp >> 2;     // 0..1: 64-code column group

    float2* pairs  = (float2*)(smp + OFF_PAIR);
    float*  znorms = (float*)(smp + OFF_ZN);
    float*  zinvs  = (float*)(smp + OFF_ZI);
    float*  mindS  = (float*)(smp + OFF_MD);   // [2][128]
    int*    miniS  = (int*)(smp + OFF_MI);     // [2][128]
    const unsigned fullB  = base + OFF_MBAR;        // full0..2
    const unsigned emptyB = fullB + 24;              // empty0..2

    if (tid == 0) {
#pragma unroll
        for (int i = 0; i < NBUF; ++i) {
            MBAR_INIT(fullB + 8u * i, 1);
            MBAR_INIT(emptyB + 8u * i, THREADS);
        }
    }
    __syncthreads();

    // ---- single-thread bulk loads of B chunks 0..2 ----------------------
    if (tid == 0) {
        const char* gb = (const char*)g_bsplit;
#pragma unroll
        for (int i = 0; i < NBUF; ++i) {
            MBAR_EXPECT_TX(fullB + 8u * i, CHUNK_B);
            BULK_G2S(base + OFF_B + i * CHUNK_B, gb + (size_t)i * CHUNK_B,
                     CHUNK_B, fullB + 8u * i);
        }
    }

    // ---- (en2, einv) pair table into smem --------------------------------
    for (int k = tid; k < KTOT; k += THREADS) pairs[k] = g_pairs[k];

    // ---- build A split tiles (thread t<128 owns token-row t) ------------
    if (tid < BM) {
        const size_t tok = (size_t)blockIdx.x * BM + tid;
        const float4* zr = reinterpret_cast<const float4*>(z + tok * D);
        float zn = 0.f;
#pragma unroll
        for (int q = 0; q < 16; ++q) {
            float4 v = zr[q];
            zn += v.x * v.x + v.y * v.y + v.z * v.z + v.w * v.w;
            float xs[4] = {v.x, v.y, v.z, v.w};
            unsigned long long p0 = 0, p1 = 0;
#pragma unroll
            for (int j = 0; j < 4; ++j) {
                float x = xs[j];
                __half h0 = __float2half_rn(x);
                float rr1 = x - __half2float(h0);
                __half h1 = __float2half_rn(rr1);
                p0 |= (unsigned long long)__half_as_ushort(h0) << (16 * j);
                p1 |= (unsigned long long)__half_as_ushort(h1) << (16 * j);
            }
            unsigned off = (unsigned)tid * ROWB + (unsigned)q * 8u;
            *(unsigned long long*)(smp + OFF_A + 0 * SPLIT_B + off) = p0;
            *(unsigned long long*)(smp + OFF_A + 1 * SPLIT_B + off) = p1;
        }
        znorms[tid] = zn;
        zinvs[tid]  = rsqrtf(zn);
    }
    __syncthreads();     // A tiles + norms visible to all warps

    // ---- HOIST: load all A fragments ONCE into registers ----------------
    const unsigned aoff = (unsigned)(lane & 15) * ROWB + (unsigned)((lane >> 4) & 1) * 16u;
    const unsigned aBase0 = base + OFF_A + (unsigned)(mgrp * 32) * ROWB + aoff;
    uint32_t A[2][2][4][4];        // [mi][split][kk][frag]
#pragma unroll
    for (int mi = 0; mi < 2; ++mi)
#pragma unroll
        for (int s = 0; s < 2; ++s)
#pragma unroll
            for (int kk = 0; kk < 4; ++kk)
                ldsm_x4(A[mi][s][kk], aBase0 + (unsigned)(mi * 16) * ROWB
                                      + (unsigned)s * SPLIT_B + (unsigned)kk * 32u);

    // this thread's 4 token rows: mi in {0,1}, rowpair in {0,1}
    int rows[2][2];
    float znr[2][2], zir[2][2];
    float* simP[2][2];
#pragma unroll
    for (int mi = 0; mi < 2; ++mi)
#pragma unroll
        for (int rp = 0; rp < 2; ++rp) {
            int r = mgrp * 32 + mi * 16 + rp * 8 + quad;
            rows[mi][rp] = r;
            znr[mi][rp] = znorms[r];
            zir[mi][rp] = zinvs[r];
            simP[mi][rp] = sim_out + ((size_t)blockIdx.x * BM + r) * (size_t)KTOT;
        }

    float mind[2][2] = {{3.4e38f, 3.4e38f}, {3.4e38f, 3.4e38f}};
    int   mini[2][2] = {{0, 0}, {0, 0}};

    const unsigned boff = ((unsigned)(lane & 7) + (unsigned)((lane >> 4) & 1) * 8u) * ROWB
                        + (unsigned)((lane >> 3) & 1) * 16u;
    const unsigned bColOff = (unsigned)(ncol * 64) * ROWB + boff;

    int buf = 0;
#pragma unroll 1
    for (int c = 0; c < NCHUNK; ++c) {
        const unsigned ph = (unsigned)((c / NBUF) & 1);
        const unsigned fb = fullB + 8u * (unsigned)buf;
        const unsigned eb = emptyB + 8u * (unsigned)buf;
        MBAR_WAIT(fb, ph);

        const unsigned Bb = base + OFF_B + (unsigned)buf * CHUNK_B + bColOff;

        float acc[2][8][4];      // [mi][nj (8 x n8)][quad-frag]
#pragma unroll
        for (int mi = 0; mi < 2; ++mi)
#pragma unroll
            for (int nj = 0; nj < 8; ++nj)
#pragma unroll
                for (int j = 0; j < 4; ++j) acc[mi][nj][j] = 0.f;

#pragma unroll
        for (int kk = 0; kk < 4; ++kk) {
#pragma unroll
            for (int sb = 0; sb < 2; ++sb) {
                uint32_t Bf[4][4];   // [n16-group 0..3][frag]
#pragma unroll
                for (int g = 0; g < 4; ++g)
                    ldsm_x4(Bf[g], Bb + (unsigned)sb * SPLIT_B
                                   + (unsigned)(g * 16) * ROWB + (unsigned)kk * 32u);

                // products: (sa,sb) in {(0,0),(1,0),(0,1)}  (drop a1b1 ~ 2^-22)
                const int nsa = (sb == 0) ? 2 : 1;
#pragma unroll
                for (int sa = 0; sa < 2; ++sa) {
                    if (sa < nsa) {
#pragma unroll
                        for (int mi = 0; mi < 2; ++mi)
#pragma unroll
                            for (int g = 0; g < 4; ++g) {
                                mma16816(acc[mi][2 * g],     A[mi][sa][kk], &Bf[g][0]);
                                mma16816(acc[mi][2 * g + 1], A[mi][sa][kk], &Bf[g][2]);
                            }
                    }
                }
            }
        }

        // done reading this buffer -> signal empty (no block barrier)
        MBAR_ARRIVE(eb);

        // producer: refill this buffer with chunk c+3 once all warps released it
        if (c + NBUF < NCHUNK && tid == 0) {
            MBAR_WAIT(eb, ph);
            const char* gb = (const char*)g_bsplit + (size_t)(c + NBUF) * CHUNK_B;
            MBAR_EXPECT_TX(fb, CHUNK_B);
            BULK_G2S(base + OFF_B + (unsigned)buf * CHUNK_B, gb, CHUNK_B, fb);
        }

        // ---- epilogue from registers (overlaps other warps' MMAs) -------
        const int cbase = c * BN + ncol * 64;
#pragma unroll
        for (int nj = 0; nj < 8; ++nj) {
            const int gci = cbase + nj * 8 + qlane * 2;
            float4 pv = *reinterpret_cast<const float4*>(pairs + gci);
#pragma unroll
            for (int mi = 0; mi < 2; ++mi) {
                const float d00 = acc[mi][nj][0], d01 = acc[mi][nj][1];
                const float d10 = acc[mi][nj][2], d11 = acc[mi][nj][3];
                float t;
                t = fmaf(-2.f, d00, znr[mi][0]) + pv.x;
                if (t < mind[mi][0]) { mind[mi][0] = t; mini[mi][0] = gci; }
                t = fmaf(-2.f, d01, znr[mi][0]) + pv.z;
                if (t < mind[mi][0]) { mind[mi][0] = t; mini[mi][0] = gci + 1; }
                t = fmaf(-2.f, d10, znr[mi][1]) + pv.x;
                if (t < mind[mi][1]) { mind[mi][1] = t; mini[mi][1] = gci; }
                t = fmaf(-2.f, d11, znr[mi][1]) + pv.z;
                if (t < mind[mi][1]) { mind[mi][1] = t; mini[mi][1] = gci + 1; }
                __stcs(reinterpret_cast<float2*>(simP[mi][0] + gci),
                       make_float2(d00 * zir[mi][0] * pv.y, d01 * zir[mi][0] * pv.w));
                __stcs(reinterpret_cast<float2*>(simP[mi][1] + gci),
                       make_float2(d10 * zir[mi][1] * pv.y, d11 * zir[mi][1] * pv.w));
            }
        }

        buf = (buf == NBUF - 1) ? 0 : buf + 1;
    }

    // ---- argmin reduce across qlane (lanes differ in bits 0..1) ---------
#pragma unroll
    for (int mi = 0; mi < 2; ++mi)
#pragma unroll
        for (int rp = 0; rp < 2; ++rp) {
            float d = mind[mi][rp];
            int   i = mini[mi][rp];
#pragma unroll
            for (int off = 1; off <= 2; off <<= 1) {
                float od = __shfl_xor_sync(0xffffffffu, d, off);
                int   oi = __shfl_xor_sync(0xffffffffu, i, off);
                if (od < d || (od == d && oi < i)) { d = od; i = oi; }
            }
            if (qlane == 0) {
                mindS[ncol * 128 + rows[mi][rp]] = d;
                miniS[ncol * 128 + rows[mi][rp]] = i;
            }
        }
    __syncthreads();

    // ---- final per-token outputs: e, z_q, loss (fp32 from global) ------
    if (tid < BM) {
        float bd = mindS[tid];
        int   bi = miniS[tid];
        {
            float d = mindS[128 + tid];
            int   i = miniS[128 + tid];
            if (d < bd || (d == bd && i < bi)) { bd = d; bi = i; }
        }
        const size_t tok = (size_t)blockIdx.x * BM + tid;
        const float4* er = reinterpret_cast<const float4*>(cbk + (size_t)bi * D);
        const float4* zr = reinterpret_cast<const float4*>(z + tok * D);
        float4* zq = reinterpret_cast<float4*>(zq_out + tok * D);
        float s = 0.f;
#pragma unroll
        for (int q = 0; q < 16; ++q) {
            float4 ev = er[q];
            float4 zv = zr[q];
            float dx = zv.x - ev.x, dy = zv.y - ev.y, dz = zv.z - ev.z, dw = zv.w - ev.w;
            s += dx * dx + dy * dy + dz * dz + dw * dw;
            zq[q] = ev;
        }
        loss_out[tok] = 1.25f * sqrtf(s);
        e_out[tok]    = (float)bi;
    }
}

extern "C" void kernel_launch(void* const* d_in, const int* in_sizes, int n_in,
                              void* d_out, int out_size) {
    const float* z   = (const float*)d_in[0];
    const float* cbk = (const float*)d_in[1];
    const int NT = in_sizes[0] / D;    // 131072

    float* out      = (float*)d_out;
    float* e_out    = out;
    float* zq_out   = e_out + NT;
    float* sim_out  = zq_out + (size_t)NT * D;
    float* loss_out = sim_out + (size_t)NT * KTOT;

    vq_prep<<<(KTOT * D + 255) / 256, 256>>>(cbk);

    cudaFuncSetAttribute(vq_mma_kernel, cudaFuncAttributeMaxDynamicSharedMemorySize, SMEM_REQ);
    vq_mma_kernel<<<NT / BM, THREADS, SMEM_REQ>>>(z, cbk, e_out, zq_out, sim_out, loss_out);
}